// round 6
// baseline (speedup 1.0000x reference)
#include <cuda_runtime.h>

// Fused: ConvTranspose3d(16->32,k3,s2,p1) + bias + BN(inference) + AvgPool2 + AvgPool2
// reduced analytically to a stride-2 3x3x3 conv with precomputed effective weights.
//
// Shapes: x (8,16,24,24,24)  w (16,32,3,3,3)  out (8,32,11,11,11)

#define CIN 16
#define COUT 32
#define DIN 24
#define OD 11
#define WS_ELEMS 13824          // 16*27*32 effective weights
#define TOTAL_THREADS 23232     // 8 b * 11 od * 11 oh * 6 owg * 4 cg

__device__ float g_ws[WS_ELEMS];
__device__ float g_kc[COUT];

// Precompute effective weights:
//   Weff[cin,co,di,dj,dk] = sum_{kd in S(di), kh in S(dj), kw in S(dk)} w[cin,co,kd,kh,kw]
//   S(0)={1,2}, S(1)={0,1,2}, S(2)={0}
// folded with BN scale and 1/64 pool factor. Layout: g_ws[(cin*27+tap)*32 + co]
// Per-channel constant: kc = bias*scale + beta - mean*scale.
__global__ void prep_kernel(const float* __restrict__ w,
                            const float* __restrict__ bias,
                            const float* __restrict__ gamma,
                            const float* __restrict__ beta,
                            const float* __restrict__ rmean,
                            const float* __restrict__ rvar) {
    int id = blockIdx.x * blockDim.x + threadIdx.x;
    if (id >= WS_ELEMS) return;
    int co  = id & 31;
    int tap = id >> 5;
    int cin = tap / 27;
    int r   = tap % 27;
    int di = r / 9, dj = (r % 9) / 3, dk = r % 3;

    const int cnt[3]    = {2, 3, 1};
    const int tab[3][3] = {{1, 2, 0}, {0, 1, 2}, {0, 0, 0}};

    const float* wb = w + (cin * COUT + co) * 27;
    float sum = 0.f;
    for (int a = 0; a < cnt[di]; ++a)
        for (int b = 0; b < cnt[dj]; ++b)
            for (int c = 0; c < cnt[dk]; ++c)
                sum += wb[tab[di][a] * 9 + tab[dj][b] * 3 + tab[dk][c]];

    float s = gamma[co] * rsqrtf(rvar[co] + 1e-5f);
    g_ws[tap * 32 + co] = sum * s * (1.f / 64.f);
    if (tap == 0)
        g_kc[co] = bias[co] * s + beta[co] - rmean[co] * s;
}

// Main conv: each thread computes 2 consecutive ow x 8 consecutive co.
// Weights staged in smem (LDS.128), x via LDG (L1/L2 resident).
__global__ void __launch_bounds__(128, 2)
conv_kernel(const float* __restrict__ x, float* __restrict__ out) {
    extern __shared__ float ws[];
    {
        float4*       dst = (float4*)ws;
        const float4* src = (const float4*)g_ws;
        for (int i = threadIdx.x; i < WS_ELEMS / 4; i += blockDim.x)
            dst[i] = src[i];
    }
    __syncthreads();

    int g = blockIdx.x * blockDim.x + threadIdx.x;
    if (g >= TOTAL_THREADS) return;

    int cg  = g & 3;         // 4 groups of 8 co
    int t   = g >> 2;
    int owg = t % 6;  t /= 6;
    int oh  = t % 11; t /= 11;
    int od  = t % 11;
    int b   = t / 11;
    int co  = cg * 8;
    int ow0 = owg * 2;       // ow0 in {0,2,4,6,8,10}; pair (ow0, ow0+1), last is single

    float a0[8], a1[8];
#pragma unroll
    for (int j = 0; j < 8; ++j) { a0[j] = 0.f; a1[j] = 0.f; }

    const float* xbase = x + ((((b * CIN) * DIN + 2 * od) * DIN + 2 * oh) * DIN + 2 * ow0);
    const float* wbase = ws + co;

    for (int cin = 0; cin < CIN; ++cin) {
        const float* xc = xbase + cin * (DIN * DIN * DIN);
        const float* wc = wbase + cin * 27 * 32;
#pragma unroll
        for (int di = 0; di < 3; ++di) {
#pragma unroll
            for (int dj = 0; dj < 3; ++dj) {
                const float* xr = xc + (di * DIN + dj) * DIN;
                float xv0 = __ldg(xr + 0);
                float xv1 = __ldg(xr + 1);
                float xv2 = __ldg(xr + 2);
                float xv3 = __ldg(xr + 3);
                float xv4 = __ldg(xr + 4);
                const float* wr = wc + (di * 9 + dj * 3) * 32;
#pragma unroll
                for (int dk = 0; dk < 3; ++dk) {
                    float4 wa  = *(const float4*)(wr + dk * 32);
                    float4 wb4 = *(const float4*)(wr + dk * 32 + 4);
                    float xa = (dk == 0) ? xv0 : (dk == 1) ? xv1 : xv2;
                    float xb = (dk == 0) ? xv2 : (dk == 1) ? xv3 : xv4;
                    a0[0] += xa * wa.x;  a0[1] += xa * wa.y;
                    a0[2] += xa * wa.z;  a0[3] += xa * wa.w;
                    a0[4] += xa * wb4.x; a0[5] += xa * wb4.y;
                    a0[6] += xa * wb4.z; a0[7] += xa * wb4.w;
                    a1[0] += xb * wa.x;  a1[1] += xb * wa.y;
                    a1[2] += xb * wa.z;  a1[3] += xb * wa.w;
                    a1[4] += xb * wb4.x; a1[5] += xb * wb4.y;
                    a1[6] += xb * wb4.z; a1[7] += xb * wb4.w;
                }
            }
        }
    }

    float* op = out + (((b * COUT + co) * OD + od) * OD + oh) * OD + ow0;
    bool has1 = (ow0 + 1) < OD;
#pragma unroll
    for (int j = 0; j < 8; ++j) {
        float k = g_kc[co + j];
        op[j * (OD * OD * OD)] = a0[j] + k;
        if (has1) op[j * (OD * OD * OD) + 1] = a1[j] + k;
    }
}

extern "C" void kernel_launch(void* const* d_in, const int* in_sizes, int n_in,
                              void* d_out, int out_size) {
    const float* x     = (const float*)d_in[0];
    const float* w     = (const float*)d_in[1];
    const float* bias  = (const float*)d_in[2];
    const float* gamma = (const float*)d_in[3];
    const float* beta  = (const float*)d_in[4];
    const float* rmean = (const float*)d_in[5];
    const float* rvar  = (const float*)d_in[6];
    float* out = (float*)d_out;

    prep_kernel<<<(WS_ELEMS + 127) / 128, 128>>>(w, bias, gamma, beta, rmean, rvar);

    cudaFuncSetAttribute(conv_kernel, cudaFuncAttributeMaxDynamicSharedMemorySize,
                         WS_ELEMS * (int)sizeof(float));
    conv_kernel<<<(TOTAL_THREADS + 127) / 128, 128, WS_ELEMS * sizeof(float)>>>(x, out);
}

// round 8
// speedup vs baseline: 1.1304x; 1.1304x over previous
#include <cuda_runtime.h>

// Fused: ConvTranspose3d(16->32,k3,s2,p1) + bias + BN(inference) + AvgPool2 + AvgPool2
// reduced analytically to a stride-2 3x3x3 conv with precomputed effective weights.
//
// Shapes: x (8,16,24,24,24)  w (16,32,3,3,3)  out (8,32,11,11,11)
//
// R6: split cin 8-ways within the CTA (512 threads = 8 cin-groups x 64 output
// slots) + in-smem tree reduction, to fix the 7.7% occupancy / 25% issue
// bottleneck seen in ncu (grid was 182 CTAs x 4 warps = 1.2 warps/SMSP).

#define CIN 16
#define COUT 32
#define DIN 24
#define OD 11
#define WS_ELEMS 13824          // 16*27*32 effective weights
#define TOTAL_OUT_SLOTS 23232   // 8 b * 11 od * 11 oh * 6 owg * 4 cg
#define SLOTS_PER_CTA 64
#define NGRP 8                  // cin groups per CTA (2 cin each)
#define SCR_STRIDE 132          // floats per slot row in reduction scratch (bank-conflict free)

__device__ float g_ws[WS_ELEMS];
__device__ float g_kc[COUT];

// Effective weights: Weff[cin,co,di,dj,dk] = sum over S(di)xS(dj)xS(dk) of w,
// S(0)={1,2}, S(1)={0,1,2}, S(2)={0}; folded with BN scale and 1/64 pool factor.
// Layout: g_ws[(cin*27+tap)*32 + co].  kc = bias*scale + beta - mean*scale.
__global__ void prep_kernel(const float* __restrict__ w,
                            const float* __restrict__ bias,
                            const float* __restrict__ gamma,
                            const float* __restrict__ beta,
                            const float* __restrict__ rmean,
                            const float* __restrict__ rvar) {
    int id = blockIdx.x * blockDim.x + threadIdx.x;
    if (id >= WS_ELEMS) return;
    int co  = id & 31;
    int tap = id >> 5;
    int cin = tap / 27;
    int r   = tap % 27;
    int di = r / 9, dj = (r % 9) / 3, dk = r % 3;

    const int cnt[3]    = {2, 3, 1};
    const int tab[3][3] = {{1, 2, 0}, {0, 1, 2}, {0, 0, 0}};

    const float* wb = w + (cin * COUT + co) * 27;
    float sum = 0.f;
    for (int a = 0; a < cnt[di]; ++a)
        for (int b = 0; b < cnt[dj]; ++b)
            for (int c = 0; c < cnt[dk]; ++c)
                sum += wb[tab[di][a] * 9 + tab[dj][b] * 3 + tab[dk][c]];

    float s = gamma[co] * rsqrtf(rvar[co] + 1e-5f);
    g_ws[tap * 32 + co] = sum * s * (1.f / 64.f);
    if (tap == 0)
        g_kc[co] = bias[co] * s + beta[co] - rmean[co] * s;
}

__global__ void __launch_bounds__(512, 2)
conv_kernel(const float* __restrict__ x, float* __restrict__ out) {
    extern __shared__ float ws[];
    {
        float4*       dst = (float4*)ws;
        const float4* src = (const float4*)g_ws;
        for (int i = threadIdx.x; i < WS_ELEMS / 4; i += blockDim.x)
            dst[i] = src[i];
    }
    __syncthreads();

    int tid = threadIdx.x;
    int grp = tid >> 6;          // cin group 0..7 (cin = 2*grp, 2*grp+1)
    int r   = tid & 63;          // output slot within CTA

    int og  = blockIdx.x * SLOTS_PER_CTA + r;   // global output slot (exact fit)
    int cg  = og & 3;            // 4 groups of 8 co
    int t   = og >> 2;
    int owg = t % 6;  t /= 6;
    int oh  = t % 11; t /= 11;
    int od  = t % 11;
    int b   = t / 11;
    int co  = cg * 8;
    int ow0 = owg * 2;           // pair (ow0, ow0+1); ow0=10 is single

    float a0[8], a1[8];
#pragma unroll
    for (int j = 0; j < 8; ++j) { a0[j] = 0.f; a1[j] = 0.f; }

    const float* xbase = x + ((((b * CIN + grp * 2) * DIN + 2 * od) * DIN + 2 * oh) * DIN + 2 * ow0);
    const float* wbase = ws + co + grp * 2 * 27 * 32;

    for (int c = 0; c < 2; ++c) {
        const float* xc = xbase + c * (DIN * DIN * DIN);
        const float* wc = wbase + c * 27 * 32;
#pragma unroll
        for (int di = 0; di < 3; ++di) {
#pragma unroll
            for (int dj = 0; dj < 3; ++dj) {
                const float* xr = xc + (di * DIN + dj) * DIN;
                float xv0 = __ldg(xr + 0);
                float xv1 = __ldg(xr + 1);
                float xv2 = __ldg(xr + 2);
                float xv3 = __ldg(xr + 3);
                float xv4 = __ldg(xr + 4);
                const float* wr = wc + (di * 9 + dj * 3) * 32;
#pragma unroll
                for (int dk = 0; dk < 3; ++dk) {
                    float4 wa  = *(const float4*)(wr + dk * 32);
                    float4 wb4 = *(const float4*)(wr + dk * 32 + 4);
                    float xa = (dk == 0) ? xv0 : (dk == 1) ? xv1 : xv2;
                    float xb = (dk == 0) ? xv2 : (dk == 1) ? xv3 : xv4;
                    a0[0] += xa * wa.x;  a0[1] += xa * wa.y;
                    a0[2] += xa * wa.z;  a0[3] += xa * wa.w;
                    a0[4] += xa * wb4.x; a0[5] += xa * wb4.y;
                    a0[6] += xa * wb4.z; a0[7] += xa * wb4.w;
                    a1[0] += xb * wa.x;  a1[1] += xb * wa.y;
                    a1[2] += xb * wa.z;  a1[3] += xb * wa.w;
                    a1[4] += xb * wb4.x; a1[5] += xb * wb4.y;
                    a1[6] += xb * wb4.z; a1[7] += xb * wb4.w;
                }
            }
        }
    }

    // ---- in-smem tree reduction over the 8 cin groups ----
    // Reuse weight smem as scratch: row stride 132 floats keeps LDS/STS.128
    // conflict-free (bank = (r*4 + grp*16) % 32, distinct across 8-lane phases).
    __syncthreads();   // everyone done reading weights

    float4* my = (float4*)(ws + r * SCR_STRIDE + grp * 16);
    my[0] = make_float4(a0[0], a0[1], a0[2], a0[3]);
    my[1] = make_float4(a0[4], a0[5], a0[6], a0[7]);
    my[2] = make_float4(a1[0], a1[1], a1[2], a1[3]);
    my[3] = make_float4(a1[4], a1[5], a1[6], a1[7]);
    __syncthreads();

    if (grp < 4) {
        float4*       d = (float4*)(ws + r * SCR_STRIDE + grp * 16);
        const float4* s = (const float4*)(ws + r * SCR_STRIDE + (grp + 4) * 16);
#pragma unroll
        for (int i = 0; i < 4; ++i) {
            float4 a = d[i], e = s[i];
            d[i] = make_float4(a.x + e.x, a.y + e.y, a.z + e.z, a.w + e.w);
        }
    }
    __syncthreads();
    if (grp < 2) {
        float4*       d = (float4*)(ws + r * SCR_STRIDE + grp * 16);
        const float4* s = (const float4*)(ws + r * SCR_STRIDE + (grp + 2) * 16);
#pragma unroll
        for (int i = 0; i < 4; ++i) {
            float4 a = d[i], e = s[i];
            d[i] = make_float4(a.x + e.x, a.y + e.y, a.z + e.z, a.w + e.w);
        }
    }
    __syncthreads();
    if (grp == 0) {
        const float* d = ws + r * SCR_STRIDE;
        const float* s = ws + r * SCR_STRIDE + 16;
        float v[16];
#pragma unroll
        for (int i = 0; i < 16; ++i) v[i] = d[i] + s[i];

        float* op = out + (((b * COUT + co) * OD + od) * OD + oh) * OD + ow0;
        bool has1 = (ow0 + 1) < OD;
#pragma unroll
        for (int j = 0; j < 8; ++j) {
            float k = g_kc[co + j];
            op[j * (OD * OD * OD)] = v[j] + k;
            if (has1) op[j * (OD * OD * OD) + 1] = v[8 + j] + k;
        }
    }
}

extern "C" void kernel_launch(void* const* d_in, const int* in_sizes, int n_in,
                              void* d_out, int out_size) {
    const float* x     = (const float*)d_in[0];
    const float* w     = (const float*)d_in[1];
    const float* bias  = (const float*)d_in[2];
    const float* gamma = (const float*)d_in[3];
    const float* beta  = (const float*)d_in[4];
    const float* rmean = (const float*)d_in[5];
    const float* rvar  = (const float*)d_in[6];
    float* out = (float*)d_out;

    prep_kernel<<<(WS_ELEMS + 127) / 128, 128>>>(w, bias, gamma, beta, rmean, rvar);

    cudaFuncSetAttribute(conv_kernel, cudaFuncAttributeMaxDynamicSharedMemorySize,
                         WS_ELEMS * (int)sizeof(float));
    conv_kernel<<<TOTAL_OUT_SLOTS / SLOTS_PER_CTA, 512, WS_ELEMS * sizeof(float)>>>(x, out);
}

// round 13
// speedup vs baseline: 1.2164x; 1.0760x over previous
#include <cuda_runtime.h>

// Fused: ConvTranspose3d(16->32,k3,s2,p1) + bias + BN(inference) + AvgPool2 + AvgPool2
// reduced analytically to a stride-2 3x3x3 conv with precomputed effective weights.
//
// Shapes: x (8,16,24,24,24)  w (16,32,3,3,3)  out (8,32,11,11,11)
//
// R8: 2ow x 4co per thread (8 accs), vectorized LDG.128 x loads, 3 CTAs/SM
// (42-reg cap), 726 CTAs x 512 threads (8 cin-groups x 64 slots), smem tree
// reduction over cin groups.

#define CIN 16
#define COUT 32
#define DIN 24
#define OD 11
#define WS_ELEMS 13824          // 16*27*32 effective weights
#define TOTAL_OUT_SLOTS 46464   // 8 b * 11 od * 11 oh * 6 owg * 8 cg
#define SLOTS_PER_CTA 64
#define NCTA 726                // 46464 / 64
#define SCR_STRIDE 68           // floats per slot row in reduction scratch (bank-conflict free)

__device__ float g_ws[WS_ELEMS];
__device__ float g_kc[COUT];

// Effective weights: Weff[cin,co,di,dj,dk] = sum over S(di)xS(dj)xS(dk) of w,
// S(0)={1,2}, S(1)={0,1,2}, S(2)={0}; folded with BN scale and 1/64 pool factor.
// Layout: g_ws[(cin*27+tap)*32 + co].  kc = bias*scale + beta - mean*scale.
__global__ void prep_kernel(const float* __restrict__ w,
                            const float* __restrict__ bias,
                            const float* __restrict__ gamma,
                            const float* __restrict__ beta,
                            const float* __restrict__ rmean,
                            const float* __restrict__ rvar) {
    int id = blockIdx.x * blockDim.x + threadIdx.x;
    if (id >= WS_ELEMS) return;
    int co  = id & 31;
    int tap = id >> 5;
    int cin = tap / 27;
    int r   = tap % 27;
    int di = r / 9, dj = (r % 9) / 3, dk = r % 3;

    const int cnt[3]    = {2, 3, 1};
    const int tab[3][3] = {{1, 2, 0}, {0, 1, 2}, {0, 0, 0}};

    const float* wb = w + (cin * COUT + co) * 27;
    float sum = 0.f;
    for (int a = 0; a < cnt[di]; ++a)
        for (int b = 0; b < cnt[dj]; ++b)
            for (int c = 0; c < cnt[dk]; ++c)
                sum += wb[tab[di][a] * 9 + tab[dj][b] * 3 + tab[dk][c]];

    float s = gamma[co] * rsqrtf(rvar[co] + 1e-5f);
    g_ws[tap * 32 + co] = sum * s * (1.f / 64.f);
    if (tap == 0)
        g_kc[co] = bias[co] * s + beta[co] - rmean[co] * s;
}

__global__ void __launch_bounds__(512, 3)
conv_kernel(const float* __restrict__ x, float* __restrict__ out) {
    extern __shared__ float ws[];
    {
        float4*       dst = (float4*)ws;
        const float4* src = (const float4*)g_ws;
        for (int i = threadIdx.x; i < WS_ELEMS / 4; i += blockDim.x)
            dst[i] = src[i];
    }
    __syncthreads();

    int tid = threadIdx.x;
    int grp = tid >> 6;          // cin group 0..7 (cin = 2*grp, 2*grp+1)
    int r   = tid & 63;          // output slot within CTA

    int og  = blockIdx.x * SLOTS_PER_CTA + r;   // global output slot (exact fit)
    int cg  = og & 7;            // 8 groups of 4 co
    int t   = og >> 3;
    int owg = t % 6;  t /= 6;
    int oh  = t % 11; t /= 11;
    int od  = t % 11;
    int b   = t / 11;
    int co  = cg * 4;
    int ow0 = owg * 2;           // pair (ow0, ow0+1); ow0=10 is single

    float a0[4], a1[4];
#pragma unroll
    for (int j = 0; j < 4; ++j) { a0[j] = 0.f; a1[j] = 0.f; }

    // 16B-aligned: row pitch 24 floats = 96B, ow offset = 4*owg floats = 16B*owg.
    const float* xbase = x + ((((b * CIN + grp * 2) * DIN + 2 * od) * DIN + 2 * oh) * DIN + 2 * ow0);
    const float* wbase = ws + co + grp * 2 * 27 * 32;

    for (int c = 0; c < 2; ++c) {
        const float* xc = xbase + c * (DIN * DIN * DIN);
        const float* wc = wbase + c * 27 * 32;
#pragma unroll
        for (int di = 0; di < 3; ++di) {
#pragma unroll
            for (int dj = 0; dj < 3; ++dj) {
                const float* xr = xc + (di * DIN + dj) * DIN;
                float4 xq  = *(const float4*)xr;   // x0..x3
                float  xv4 = __ldg(xr + 4);        // x4
                const float* wr = wc + (di * 9 + dj * 3) * 32;
#pragma unroll
                for (int dk = 0; dk < 3; ++dk) {
                    float4 w4 = *(const float4*)(wr + dk * 32);
                    float xa = (dk == 0) ? xq.x : (dk == 1) ? xq.y : xq.z;
                    float xb = (dk == 0) ? xq.z : (dk == 1) ? xq.w : xv4;
                    a0[0] += xa * w4.x; a0[1] += xa * w4.y;
                    a0[2] += xa * w4.z; a0[3] += xa * w4.w;
                    a1[0] += xb * w4.x; a1[1] += xb * w4.y;
                    a1[2] += xb * w4.z; a1[3] += xb * w4.w;
                }
            }
        }
    }

    // ---- in-smem tree reduction over the 8 cin groups ----
    // Scratch row stride 68 floats: lane bank step = 68 % 32 = 4 -> the 8 lanes
    // of each STS/LDS.128 phase hit distinct banks (conflict-free).
    __syncthreads();   // everyone done reading weights

    float4* my = (float4*)(ws + r * SCR_STRIDE + grp * 8);
    my[0] = make_float4(a0[0], a0[1], a0[2], a0[3]);
    my[1] = make_float4(a1[0], a1[1], a1[2], a1[3]);
    __syncthreads();

    if (grp < 4) {
        float4*       d = (float4*)(ws + r * SCR_STRIDE + grp * 8);
        const float4* s = (const float4*)(ws + r * SCR_STRIDE + (grp + 4) * 8);
#pragma unroll
        for (int i = 0; i < 2; ++i) {
            float4 a = d[i], e = s[i];
            d[i] = make_float4(a.x + e.x, a.y + e.y, a.z + e.z, a.w + e.w);
        }
    }
    __syncthreads();
    if (grp < 2) {
        float4*       d = (float4*)(ws + r * SCR_STRIDE + grp * 8);
        const float4* s = (const float4*)(ws + r * SCR_STRIDE + (grp + 2) * 8);
#pragma unroll
        for (int i = 0; i < 2; ++i) {
            float4 a = d[i], e = s[i];
            d[i] = make_float4(a.x + e.x, a.y + e.y, a.z + e.z, a.w + e.w);
        }
    }
    __syncthreads();
    if (grp == 0) {
        const float* d = ws + r * SCR_STRIDE;
        const float* s = ws + r * SCR_STRIDE + 8;
        float v[8];
#pragma unroll
        for (int i = 0; i < 8; ++i) v[i] = d[i] + s[i];

        float* op = out + (((b * COUT + co) * OD + od) * OD + oh) * OD + ow0;
        bool has1 = (ow0 + 1) < OD;
#pragma unroll
        for (int j = 0; j < 4; ++j) {
            float k = g_kc[co + j];
            op[j * (OD * OD * OD)] = v[j] + k;
            if (has1) op[j * (OD * OD * OD) + 1] = v[4 + j] + k;
        }
    }
}

extern "C" void kernel_launch(void* const* d_in, const int* in_sizes, int n_in,
                              void* d_out, int out_size) {
    const float* x     = (const float*)d_in[0];
    const float* w     = (const float*)d_in[1];
    const float* bias  = (const float*)d_in[2];
    const float* gamma = (const float*)d_in[3];
    const float* beta  = (const float*)d_in[4];
    const float* rmean = (const float*)d_in[5];
    const float* rvar  = (const float*)d_in[6];
    float* out = (float*)d_out;

    prep_kernel<<<(WS_ELEMS + 127) / 128, 128>>>(w, bias, gamma, beta, rmean, rvar);

    cudaFuncSetAttribute(conv_kernel, cudaFuncAttributeMaxDynamicSharedMemorySize,
                         WS_ELEMS * (int)sizeof(float));
    conv_kernel<<<NCTA, 512, WS_ELEMS * sizeof(float)>>>(x, out);
}